// round 12
// baseline (speedup 1.0000x reference)
#include <cuda_runtime.h>

// BoxLoss: 3-scale YOLO box loss. ONE launch, 32 blocks (1 image each),
// 192 threads = 3 scale groups x 64 lanes (R10 skeleton — measured best).
// Post-gather path shortened:
//  - warp sums as exact fixed-point (contrib*2^30) via 3 independent
//    REDUX.ADD ops (24/40 split + count) instead of a 5-deep SHFL chain
//  - group combine in plain smem (u64+int stores), float-only math
//    (__fdividef + cvt.rni) in the combiner
//  - ONE global counting atomicAdd (tag@56 | fix56); the 96th arriver has
//    the exact total in registers and writes the scalar. No polling/fences.

#define NT   50
#define NA   3
#define NC   85
#define BMAX 32
#define THRESH 0.5f
#define FULL 0xffffffffu
#define FIXF 1073741824.0f           // 2^30, exact in float
#define FIX  1073741824.0
#define GTAG (1ull << 56)
#define GVAL ((1ull << 56) - 1ull)

__device__ unsigned long long g_acc = 0ull;

__device__ __forceinline__ void st_cg64(unsigned long long* p, unsigned long long v) {
    asm volatile("st.global.cg.u64 [%0], %1;" :: "l"(p), "l"(v) : "memory");
}
__device__ __forceinline__ void bar_group(int id) {
    asm volatile("bar.sync %0, 64;" :: "r"(id) : "memory");
}

__global__ void __launch_bounds__(192, 1)
box_loss_fused(const float* __restrict__ out0, const float* __restrict__ anc0,
               const float* __restrict__ out1, const float* __restrict__ anc1,
               const float* __restrict__ out2, const float* __restrict__ anc2,
               const float* __restrict__ targets,
               float* __restrict__ result, float invB)
{
    const int b    = blockIdx.x;
    const int B    = gridDim.x;
    const int tid  = threadIdx.x;
    const int g    = tid >> 6;          // scale group 0..2
    const int l    = tid & 63;          // lane in group (== target index)
    const int lane = tid & 31;
    const bool odd = (l >= 32);

    __shared__ int                skey18[3][18];  // warp-odd keys (targets 32..49)
    __shared__ unsigned long long sfix[6];        // per-warp fixed-point sums
    __shared__ int                scnt[6];

    const float* out = (g == 0) ? out0 : (g == 1) ? out1 : out2;
    const float* anc = (g == 0) ? anc0 : (g == 1) ? anc1 : anc2;
    const int    G   = (g == 0) ? 52   : (g == 1) ? 26   : 13;
    const float  fG  = (float)G;

    // ---- all independent global loads issued immediately ----
    const float aw0 = __ldg(anc + 0), ah0 = __ldg(anc + 1);
    const float aw1 = __ldg(anc + 2), ah1 = __ldg(anc + 3);
    const float aw2 = __ldg(anc + 4), ah2 = __ldg(anc + 5);

    float x = 0.f, y = 0.f, w = 0.f, h = 0.f;
    if (l < NT) {
        const float* tg = targets + ((size_t)b * NT + l) * 5;
        x = __ldg(tg + 1); y = __ldg(tg + 2);
        w = __ldg(tg + 3); h = __ldg(tg + 4);
    }

    const bool  valid = (l < NT) && !(x == 0.f && y == 0.f && w == 0.f && h == 0.f);
    const float tx = x * fG, ty = y * fG, tw = w * fG, th = h * fG;
    const float cx = floorf(tx), cy = floorf(ty);
    const int   icx = (int)cx,   icy = (int)cy;
    const bool  inb = valid && icx >= 0 && icx < G && icy >= 0 && icy < G;

    // ---- IoU vs 3 anchors (areas from rect diffs, matching reference) ----
    const float zx = tx - cx - 0.5f, zy = ty - cy - 0.5f;
    const float t0 = zx - tw * 0.5f, t1 = zy - th * 0.5f;
    const float t2 = zx + tw * 0.5f, t3 = zy + th * 0.5f;
    const float area_t = (t2 - t0) * (t3 - t1);

    float overlap = -1.f;
    int   best = 0;
    #pragma unroll
    for (int a = 0; a < NA; a++) {
        const float w2 = ((a == 0) ? aw0 : (a == 1) ? aw1 : aw2) * 0.5f;
        const float h2 = ((a == 0) ? ah0 : (a == 1) ? ah1 : ah2) * 0.5f;
        const float x0 = fmaxf(t0, -w2), y0 = fmaxf(t1, -h2);
        const float x1 = fminf(t2,  w2), y1 = fminf(t3,  h2);
        const float inter  = (x0 < x1 && y0 < y1) ? (x1 - x0) * (y1 - y0) : 0.f;
        const float area_a = (2.f * w2) * (2.f * h2);
        const float iou = inter / (area_t + area_a - inter);
        if (iou > overlap) { overlap = iou; best = a; }   // first-max wins
    }

    const int key = (inb && overlap > THRESH) ? (best * G + icy) * G + icx : -1;
    if (odd && l < NT) skey18[g][l - 32] = key;

    // ---- speculative gather (best anchor only), overlaps barrier+dup ----
    float px = 0.f, py = 0.f, pw = 1.f, ph = 1.f;
    if (key >= 0) {
        const float* c = out + ((long long)b * NA * G * G + key) * (long long)NC;
        px = __ldg(c + 0); py = __ldg(c + 1);
        pw = __ldg(c + 2); ph = __ldg(c + 3);
    }
    bar_group(g + 1);          // skey18 visible within the group

    // ---- collision resolution: last target index wins ----
    const unsigned mmask = __match_any_sync(FULL, key);
    bool win = (key >= 0) && ((31 - __clz(mmask)) == lane);
    if (!odd && win) {
        bool dup = false;
        #pragma unroll
        for (int j = 0; j < 18; j++)
            dup |= (skey18[g][j] == key);
        win = !dup;
    }

    float contrib = 0.f;
    if (win) {
        const float dx = px - tx, dy = py - ty;
        const float rw = rsqrtf(pw) - rsqrtf(tw);
        const float rh = rsqrtf(ph) - rsqrtf(th);
        contrib = dx * dx + dy * dy + rw * rw + rh * rh;
    }

    // ---- exact fixed-point warp sum: 3 independent REDUX.ADD ----
    // contrib <= ~2^13 -> contrib*2^30 <= 2^43; lo24 sums <= 2^29, hi sums <= 2^28.
    const unsigned long long c64 = (unsigned long long)(contrib * FIXF);
    const unsigned slo = __reduce_add_sync(FULL, (unsigned)(c64 & 0xFFFFFFull));
    const unsigned shi = __reduce_add_sync(FULL, (unsigned)(c64 >> 24));
    const int      cnt = __reduce_add_sync(FULL, win ? 1 : 0);

    const int wid = tid >> 5;
    if (lane == 0) {
        sfix[wid] = ((unsigned long long)shi << 24) + (unsigned long long)slo;
        scnt[wid] = cnt;
    }
    bar_group(g + 1);

    // ---- group combine (integer adds, float-only math) + ONE global atomic --
    if (l == 0) {
        const unsigned long long tot = sfix[2 * g] + sfix[2 * g + 1];
        const int                n   = scnt[2 * g] + scnt[2 * g + 1];
        long long gfix = 0ll;
        if (n > 0)   // loss*2^30 = tot / (2n), computed in float (<=6e-8 rel)
            gfix = (long long)(__fdividef((float)tot, (float)(2 * n)));
        const unsigned long long gpack = GTAG | (unsigned long long)gfix;
        const unsigned long long gold  = atomicAdd(&g_acc, gpack);
        if ((gold >> 56) == (unsigned long long)(3 * B - 1)) {
            // 96th arrival: exact total already in registers
            const unsigned long long gtot = gold + gpack;
            const double s = (double)(long long)(gtot & GVAL) * (1.0 / FIX);
            result[0] = (float)s * invB;
            st_cg64(&g_acc, 0ull);            // re-arm for next graph replay
        }
    }
}

extern "C" void kernel_launch(void* const* d_in, const int* in_sizes, int n_in,
                              void* d_out, int out_size)
{
    const float* out0 = (const float*)d_in[0];
    const float* anc0 = (const float*)d_in[1];
    const float* out1 = (const float*)d_in[2];
    const float* anc1 = (const float*)d_in[3];
    const float* out2 = (const float*)d_in[4];
    const float* anc2 = (const float*)d_in[5];
    const float* tgts = (const float*)d_in[6];

    int B = in_sizes[6] / (NT * 5);
    if (B > BMAX) B = BMAX;

    box_loss_fused<<<B, 192>>>(out0, anc0, out1, anc1, out2, anc2, tgts,
                               (float*)d_out, 1.0f / (float)B);
}

// round 13
// speedup vs baseline: 1.0435x; 1.0435x over previous
#include <cuda_runtime.h>

// BoxLoss: 3-scale YOLO box loss. ONE launch, 32 blocks (1 image each),
// 192 threads = 3 scale groups x 64 lanes (R10 skeleton — measured best).
// Tail algebra restructured: loss_g = (sumE+sumO)/(2n), so each WARP
// publishes warpsum/(2n) on its own once it knows the group count n.
// Only the 4-byte counts cross warps (smem); the shfl reduce runs after
// that barrier; each warp does its own fixed-point pack + ONE global
// counting atomicAdd (192 arrivals, same-address ATOMG pipelines ~free).
// The 192nd arriver holds the exact integer total in registers -> writes
// the scalar. No polling, no fences, no designated-combiner hand-off.

#define NT   50
#define NA   3
#define NC   85
#define BMAX 32
#define THRESH 0.5f
#define FULL 0xffffffffu
#define FIXF 1073741824.0f           // 2^30 exact in float
#define FIX  1073741824.0
#define GTAG (1ull << 56)
#define GVAL ((1ull << 56) - 1ull)

__device__ unsigned long long g_acc = 0ull;

__device__ __forceinline__ void st_cg64(unsigned long long* p, unsigned long long v) {
    asm volatile("st.global.cg.u64 [%0], %1;" :: "l"(p), "l"(v) : "memory");
}

__global__ void __launch_bounds__(192, 1)
box_loss_fused(const float* __restrict__ out0, const float* __restrict__ anc0,
               const float* __restrict__ out1, const float* __restrict__ anc1,
               const float* __restrict__ out2, const float* __restrict__ anc2,
               const float* __restrict__ targets,
               float* __restrict__ result, float invB)
{
    const int b    = blockIdx.x;
    const int B    = gridDim.x;
    const int tid  = threadIdx.x;
    const int g    = tid >> 6;          // scale group 0..2
    const int l    = tid & 63;          // lane in group (== target index)
    const int lane = tid & 31;
    const int wid  = tid >> 5;          // 0..5
    const bool odd = (l >= 32);

    __shared__ int skey18[3][18];       // warp-odd keys (targets 32..49)
    __shared__ int scnt[6];             // per-warp winner counts

    const float* out = (g == 0) ? out0 : (g == 1) ? out1 : out2;
    const float* anc = (g == 0) ? anc0 : (g == 1) ? anc1 : anc2;
    const int    G   = (g == 0) ? 52   : (g == 1) ? 26   : 13;
    const float  fG  = (float)G;

    // ---- all independent global loads issued immediately ----
    const float aw0 = __ldg(anc + 0), ah0 = __ldg(anc + 1);
    const float aw1 = __ldg(anc + 2), ah1 = __ldg(anc + 3);
    const float aw2 = __ldg(anc + 4), ah2 = __ldg(anc + 5);

    float x = 0.f, y = 0.f, w = 0.f, h = 0.f;
    if (l < NT) {
        const float* tg = targets + ((size_t)b * NT + l) * 5;
        x = __ldg(tg + 1); y = __ldg(tg + 2);
        w = __ldg(tg + 3); h = __ldg(tg + 4);
    }

    const bool  valid = (l < NT) && !(x == 0.f && y == 0.f && w == 0.f && h == 0.f);
    const float tx = x * fG, ty = y * fG, tw = w * fG, th = h * fG;
    const float cx = floorf(tx), cy = floorf(ty);
    const int   icx = (int)cx,   icy = (int)cy;
    const bool  inb = valid && icx >= 0 && icx < G && icy >= 0 && icy < G;

    // ---- IoU vs 3 anchors (areas from rect diffs, matching reference) ----
    const float zx = tx - cx - 0.5f, zy = ty - cy - 0.5f;
    const float t0 = zx - tw * 0.5f, t1 = zy - th * 0.5f;
    const float t2 = zx + tw * 0.5f, t3 = zy + th * 0.5f;
    const float area_t = (t2 - t0) * (t3 - t1);

    float overlap = -1.f;
    int   best = 0;
    #pragma unroll
    for (int a = 0; a < NA; a++) {
        const float w2 = ((a == 0) ? aw0 : (a == 1) ? aw1 : aw2) * 0.5f;
        const float h2 = ((a == 0) ? ah0 : (a == 1) ? ah1 : ah2) * 0.5f;
        const float x0 = fmaxf(t0, -w2), y0 = fmaxf(t1, -h2);
        const float x1 = fminf(t2,  w2), y1 = fminf(t3,  h2);
        const float inter  = (x0 < x1 && y0 < y1) ? (x1 - x0) * (y1 - y0) : 0.f;
        const float area_a = (2.f * w2) * (2.f * h2);
        const float iou = inter / (area_t + area_a - inter);
        if (iou > overlap) { overlap = iou; best = a; }   // first-max wins
    }

    const int key = (inb && overlap > THRESH) ? (best * G + icy) * G + icx : -1;

    // ---- producer: odd warp exports keys, arrives (non-blocking) ----
    if (odd) {
        if (l < NT) skey18[g][l - 32] = key;
        asm volatile("bar.arrive %0, 64;" :: "r"(g + 1) : "memory");
    }

    // ---- speculative gather (best anchor only) ----
    float px = 0.f, py = 0.f, pw = 1.f, ph = 1.f;
    if (key >= 0) {
        const float* c = out + ((long long)b * NA * G * G + key) * (long long)NC;
        px = __ldg(c + 0); py = __ldg(c + 1);
        pw = __ldg(c + 2); ph = __ldg(c + 3);
    }

    // ---- dup resolution: last target index wins ----
    const unsigned mmask = __match_any_sync(FULL, key);
    bool win = (key >= 0) && ((31 - __clz(mmask)) == lane);
    if (!odd) {
        asm volatile("bar.sync %0, 64;" :: "r"(g + 1) : "memory");
        if (win) {
            bool dup = false;
            #pragma unroll
            for (int j = 0; j < 18; j++)
                dup |= (skey18[g][j] == key);
            win = !dup;
        }
    }

    float contrib = 0.f;
    if (win) {
        const float dx = px - tx, dy = py - ty;
        const float rw = rsqrtf(pw) - rsqrtf(tw);
        const float rh = rsqrtf(ph) - rsqrtf(th);
        contrib = dx * dx + dy * dy + rw * rw + rh * rh;
    }

    // ---- exchange ONLY the counts across the warp pair ----
    const int cnt = __popc(__ballot_sync(FULL, win));
    if (lane == 0) scnt[wid] = cnt;
    asm volatile("bar.sync %0, 64;" :: "r"(g + 4) : "memory");

    // ---- warp reduce (overlaps the other warp's straggle) ----
    float sum = contrib;
    #pragma unroll
    for (int off = 16; off > 0; off >>= 1)
        sum += __shfl_down_sync(FULL, sum, off);

    // ---- per-warp publish: warpsum/(2n) as fixed-point, ONE counting atomic
    if (lane == 0) {
        const int n = scnt[wid] + scnt[wid ^ 1];     // group count
        long long fix = 0ll;
        if (n > 0)
            fix = (long long)(__fdividef(sum, 2.0f * (float)n) * FIXF);
        const unsigned long long gpack = GTAG | (unsigned long long)fix;
        const unsigned long long gold  = atomicAdd(&g_acc, gpack);
        if ((gold >> 56) == (unsigned long long)(6 * B - 1)) {
            // 192nd arrival: exact integer total already in registers
            const unsigned long long gtot = gold + gpack;
            const double s = (double)(long long)(gtot & GVAL) * (1.0 / FIX);
            result[0] = (float)s * invB;
            st_cg64(&g_acc, 0ull);               // re-arm for next replay
        }
    }
}

extern "C" void kernel_launch(void* const* d_in, const int* in_sizes, int n_in,
                              void* d_out, int out_size)
{
    const float* out0 = (const float*)d_in[0];
    const float* anc0 = (const float*)d_in[1];
    const float* out1 = (const float*)d_in[2];
    const float* anc1 = (const float*)d_in[3];
    const float* out2 = (const float*)d_in[4];
    const float* anc2 = (const float*)d_in[5];
    const float* tgts = (const float*)d_in[6];

    int B = in_sizes[6] / (NT * 5);
    if (B > BMAX) B = BMAX;

    box_loss_fused<<<B, 192>>>(out0, anc0, out1, anc1, out2, anc2, tgts,
                               (float*)d_out, 1.0f / (float)B);
}